// round 2
// baseline (speedup 1.0000x reference)
#include <cuda_runtime.h>
#include <cuda_fp8.h>
#include <cstdint>

#define DIM 2048
#define NB  (DIM / 32)   // 64 scale blocks per row

// ---------------- scratch (device globals: no allocation allowed) ----------------
__device__ uint8_t g_xq[DIM * DIM];   // x quantized e4m3
__device__ uint8_t g_wq[DIM * DIM];   // w quantized e4m3
__device__ float   g_sx[DIM * NB];    // x block scales
__device__ float   g_sw[DIM * NB];    // w block scales

// ---------------- quantize: per 32-elem block, fp32 scale + e4m3 elems ----------------
__global__ void quant_kernel(const float* __restrict__ src,
                             uint8_t* __restrict__ q,
                             float* __restrict__ sc) {
    const int idx = blockIdx.x * blockDim.x + threadIdx.x;   // one 32-elem block
    const float4* p = reinterpret_cast<const float4*>(src) + (size_t)idx * 8;
    float4 v[8];
    float m = 0.f;
#pragma unroll
    for (int i = 0; i < 8; i++) {
        v[i] = p[i];
        m = fmaxf(m, fmaxf(fmaxf(fabsf(v[i].x), fabsf(v[i].y)),
                           fmaxf(fabsf(v[i].z), fabsf(v[i].w))));
    }
    const float s = fmaxf(__fdiv_rn(m, 448.0f), 1e-30f);
    sc[idx] = s;

    const float* e = reinterpret_cast<const float*>(v);
    uint32_t w[8];
#pragma unroll
    for (int g = 0; g < 8; g++) {
        uint32_t pk = 0;
#pragma unroll
        for (int j = 0; j < 4; j++) {
            float qv = __fdiv_rn(e[g * 4 + j], s);           // RN div, matches jnp
            uint8_t b = (uint8_t)__nv_cvt_float_to_fp8(qv, __NV_SATFINITE, __NV_E4M3);
            pk |= ((uint32_t)b) << (8 * j);
        }
        w[g] = pk;
    }
    uint4* qp = reinterpret_cast<uint4*>(q) + (size_t)idx * 2;
    qp[0] = make_uint4(w[0], w[1], w[2], w[3]);
    qp[1] = make_uint4(w[4], w[5], w[6], w[7]);
}

// ---------------- GEMM with per-block fp32 scaling on fp8 tensor cores ----------------
// CTA tile 128x128, K-chunk = 128 e4m3 bytes (4 scale-blocks), double-buffered cp.async.
// Smem stage: A 16KB | B 16KB | SX 2KB | SW 2KB  => 36864 B; two stages = 73728 B.
static constexpr int STG      = 36864;
static constexpr int OFF_B    = 16384;
static constexpr int OFF_SX   = 32768;
static constexpr int OFF_SW   = 34816;
static constexpr int SMEM_TOT = 2 * STG;

#define SWZ_OFF(r, c) (((r) * 128) + ((((c) ^ ((r) & 7)) & 7) << 4))

__device__ __forceinline__ void cp16(uint32_t saddr, const void* gptr) {
    asm volatile("cp.async.cg.shared.global [%0], [%1], 16;"
                 :: "r"(saddr), "l"(__cvta_generic_to_global(gptr)));
}
__device__ __forceinline__ void cp16ca(uint32_t saddr, const void* gptr) {
    asm volatile("cp.async.ca.shared.global [%0], [%1], 16;"
                 :: "r"(saddr), "l"(__cvta_generic_to_global(gptr)));
}

__global__ void __launch_bounds__(256)
gemm_kernel(const float* __restrict__ bias, float* __restrict__ out) {
    extern __shared__ char smem[];
    const uint32_t sbase = (uint32_t)__cvta_generic_to_shared(smem);
    const int tid  = threadIdx.x;
    const int lane = tid & 31, warp = tid >> 5;
    const int m0 = blockIdx.y * 128, n0 = blockIdx.x * 128;
    const int wm0 = (warp >> 2) * 64, wn0 = (warp & 3) * 32;

    float acc[4][4][4];
#pragma unroll
    for (int i = 0; i < 4; i++)
#pragma unroll
        for (int j = 0; j < 4; j++)
#pragma unroll
            for (int k = 0; k < 4; k++) acc[i][j][k] = 0.f;

    // ---- stage loader: A/B tiles (swizzled) + scales ----
    auto load_stage = [&](int kc, int st) {
        const uint32_t sb = sbase + st * STG;
#pragma unroll
        for (int i = 0; i < 4; i++) {
            const int idx = tid * 4 + i;          // 0..1023 chunk ids
            const int r = idx >> 3, c = idx & 7;  // row 0..127, 16B chunk 0..7
            cp16(sb + SWZ_OFF(r, c),
                 g_xq + (size_t)(m0 + r) * DIM + kc * 128 + c * 16);
            cp16(sb + OFF_B + SWZ_OFF(r, c),
                 g_wq + (size_t)(n0 + r) * DIM + kc * 128 + c * 16);
        }
        if (tid < 128) {
            cp16ca(sb + OFF_SX + tid * 16,
                   g_sx + (size_t)(m0 + tid) * NB + kc * 4);
        } else {
            const int t = tid - 128;
            cp16ca(sb + OFF_SW + t * 16,
                   g_sw + (size_t)(n0 + t) * NB + kc * 4);
        }
    };

    load_stage(0, 0);
    asm volatile("cp.async.commit_group;" ::: "memory");

#pragma unroll 1
    for (int kc = 0; kc < 16; kc++) {
        const int st = kc & 1;
        if (kc + 1 < 16) load_stage(kc + 1, st ^ 1);
        asm volatile("cp.async.commit_group;" ::: "memory");
        asm volatile("cp.async.wait_group 1;" ::: "memory");
        __syncthreads();

        const uint32_t sb = sbase + st * STG;
        const char* ss = smem + st * STG;

#pragma unroll
        for (int b = 0; b < 4; b++) {   // 4 scale-blocks of K=32 within the 128B chunk
            // A fragments: 4 m-tiles of 16 rows
            uint32_t af[4][4];
#pragma unroll
            for (int mt = 0; mt < 4; mt++) {
                const int r = wm0 + mt * 16 + (lane & 7) + ((lane >> 3) & 1) * 8;
                const int c = 2 * b + (lane >> 4);
                const uint32_t ad = sb + SWZ_OFF(r, c);
                asm volatile("ldmatrix.sync.aligned.m8n8.x4.shared.b16 {%0,%1,%2,%3}, [%4];"
                             : "=r"(af[mt][0]), "=r"(af[mt][1]), "=r"(af[mt][2]), "=r"(af[mt][3])
                             : "r"(ad));
            }
            // B fragments: 4 n-tiles of 8 cols
            uint32_t bf[4][2];
#pragma unroll
            for (int nt = 0; nt < 4; nt++) {
                const int r = wn0 + nt * 8 + (lane & 7);
                const int c = 2 * b + ((lane >> 3) & 1);
                const uint32_t ad = sb + OFF_B + SWZ_OFF(r, c);
                asm volatile("ldmatrix.sync.aligned.m8n8.x2.shared.b16 {%0,%1}, [%2];"
                             : "=r"(bf[nt][0]), "=r"(bf[nt][1])
                             : "r"(ad));
            }
            // scales for this block
            float sxa[4], sxb[4], swa[4], swb[4];
#pragma unroll
            for (int mt = 0; mt < 4; mt++) {
                const int r = wm0 + mt * 16 + (lane >> 2);
                sxa[mt] = *reinterpret_cast<const float*>(ss + OFF_SX + r * 16 + b * 4);
                sxb[mt] = *reinterpret_cast<const float*>(ss + OFF_SX + (r + 8) * 16 + b * 4);
            }
#pragma unroll
            for (int nt = 0; nt < 4; nt++) {
                const int cj = wn0 + nt * 8 + ((lane & 3) << 1);
                swa[nt] = *reinterpret_cast<const float*>(ss + OFF_SW + cj * 16 + b * 4);
                swb[nt] = *reinterpret_cast<const float*>(ss + OFF_SW + (cj + 1) * 16 + b * 4);
            }
            // 16 mmas, per-block scale applied in fp32
#pragma unroll
            for (int mt = 0; mt < 4; mt++)
#pragma unroll
                for (int nt = 0; nt < 4; nt++) {
                    float d0, d1, d2, d3;
                    asm volatile(
                        "mma.sync.aligned.m16n8k32.row.col.f32.e4m3.e4m3.f32 "
                        "{%0,%1,%2,%3}, {%4,%5,%6,%7}, {%8,%9}, {%10,%11,%12,%13};"
                        : "=f"(d0), "=f"(d1), "=f"(d2), "=f"(d3)
                        : "r"(af[mt][0]), "r"(af[mt][1]), "r"(af[mt][2]), "r"(af[mt][3]),
                          "r"(bf[nt][0]), "r"(bf[nt][1]),
                          "f"(0.f), "f"(0.f), "f"(0.f), "f"(0.f));
                    acc[mt][nt][0] = fmaf(sxa[mt] * swa[nt], d0, acc[mt][nt][0]);
                    acc[mt][nt][1] = fmaf(sxa[mt] * swb[nt], d1, acc[mt][nt][1]);
                    acc[mt][nt][2] = fmaf(sxb[mt] * swa[nt], d2, acc[mt][nt][2]);
                    acc[mt][nt][3] = fmaf(sxb[mt] * swb[nt], d3, acc[mt][nt][3]);
                }
        }
        __syncthreads();
    }

    // ---- epilogue: add bias, store fp32 ----
#pragma unroll
    for (int mt = 0; mt < 4; mt++) {
        const int r0 = m0 + wm0 + mt * 16 + (lane >> 2);
#pragma unroll
        for (int nt = 0; nt < 4; nt++) {
            const int cj = n0 + wn0 + nt * 8 + ((lane & 3) << 1);
            const float2 bz = *reinterpret_cast<const float2*>(bias + cj);
            float2 o0 = make_float2(acc[mt][nt][0] + bz.x, acc[mt][nt][1] + bz.y);
            float2 o1 = make_float2(acc[mt][nt][2] + bz.x, acc[mt][nt][3] + bz.y);
            *reinterpret_cast<float2*>(out + (size_t)r0 * DIM + cj) = o0;
            *reinterpret_cast<float2*>(out + (size_t)(r0 + 8) * DIM + cj) = o1;
        }
    }
}

// ---------------- launch ----------------
extern "C" void kernel_launch(void* const* d_in, const int* in_sizes, int n_in,
                              void* d_out, int out_size) {
    const float* x    = (const float*)d_in[0];
    const float* w    = (const float*)d_in[1];
    const float* bias = (const float*)d_in[2];
    float* out = (float*)d_out;

    void *xq, *wq, *sx, *sw;
    cudaGetSymbolAddress(&xq, g_xq);
    cudaGetSymbolAddress(&wq, g_wq);
    cudaGetSymbolAddress(&sx, g_sx);
    cudaGetSymbolAddress(&sw, g_sw);

    cudaFuncSetAttribute(gemm_kernel, cudaFuncAttributeMaxDynamicSharedMemorySize, SMEM_TOT);

    const int nblk = DIM * DIM / 32;   // 131072 quant blocks per tensor
    quant_kernel<<<nblk / 256, 256>>>(x, (uint8_t*)xq, (float*)sx);
    quant_kernel<<<nblk / 256, 256>>>(w, (uint8_t*)wq, (float*)sw);
    gemm_kernel<<<dim3(16, 16), 256, SMEM_TOT>>>(bias, out);
}